// round 6
// baseline (speedup 1.0000x reference)
#include <cuda_runtime.h>
#include <cstdint>

#define BATCH 32
#define TT    2048
#define FF    64
#define HH    256
#define G3    768
#define OUTD  64
#define EPSF  1e-3f

#define CLUSTER 8
#define NCTA    128            // 16 clusters x 8
#define THREADS 384            // 12 warps: (col-group 0..2) x (kq 0..3)

typedef unsigned long long ull;

// ---- device scratch ----
__device__ float g_xb1[(size_t)BATCH * TT * G3];
__device__ float g_xb2[(size_t)BATCH * TT * G3];
__device__ float g_h2[BATCH * HH];

// ---- helpers ----
__device__ __forceinline__ ull pack2(float lo, float hi) {
    ull r; asm("mov.b64 %0, {%1, %2};" : "=l"(r) : "f"(lo), "f"(hi)); return r;
}
__device__ __forceinline__ void unpack2(ull v, float& lo, float& hi) {
    asm("mov.b64 {%0, %1}, %2;" : "=f"(lo), "=f"(hi) : "l"(v));
}
__device__ __forceinline__ ull fma2(ull a, ull b, ull c) {
    ull d; asm("fma.rn.f32x2 %0, %1, %2, %3;" : "=l"(d) : "l"(a), "l"(b), "l"(c)); return d;
}
__device__ __forceinline__ ull add2(ull a, ull b) {
    ull d; asm("add.rn.f32x2 %0, %1, %2;" : "=l"(d) : "l"(a), "l"(b)); return d;
}
__device__ __forceinline__ uint32_t smem_u32(const void* p) {
    uint32_t a;
    asm("{ .reg .u64 t; cvta.to.shared.u64 t, %1; cvt.u32.u64 %0, t; }" : "=r"(a) : "l"(p));
    return a;
}
__device__ __forceinline__ void st_cluster_f32(uint32_t la, float v, uint32_t peer) {
    uint32_t ra;
    asm("mapa.shared::cluster.u32 %0, %1, %2;" : "=r"(ra) : "r"(la), "r"(peer));
    asm volatile("st.shared::cluster.f32 [%0], %1;" :: "r"(ra), "f"(v) : "memory");
}
__device__ __forceinline__ void cluster_arrive_() {
    asm volatile("barrier.cluster.arrive.aligned;" ::: "memory");
}
__device__ __forceinline__ void cluster_wait_() {
    asm volatile("barrier.cluster.wait.aligned;" ::: "memory");
}
__device__ __forceinline__ void cluster_sync_() { cluster_arrive_(); cluster_wait_(); }
__device__ __forceinline__ uint32_t cluster_rank() {
    uint32_t r; asm("mov.u32 %0, %%cluster_ctarank;" : "=r"(r)); return r;
}
__device__ __forceinline__ float fsig(float x) {
    float e; asm("ex2.approx.ftz.f32 %0, %1;" : "=f"(e) : "f"(-1.4426950408889634f * x));
    float r; asm("rcp.approx.ftz.f32 %0, %1;" : "=f"(r) : "f"(1.f + e));
    return r;
}
__device__ __forceinline__ float ftanh(float x) {
    float e; asm("ex2.approx.ftz.f32 %0, %1;" : "=f"(e) : "f"(2.8853900817779268f * x)); // e^{2x}
    float r; asm("rcp.approx.ftz.f32 %0, %1;" : "=f"(r) : "f"(1.f + e));
    return 1.f - 2.f * r;
}

// ============================================================================
// Kernel 1: LayerNorm + input projection of layer 1.
//   g_xb1[b,t,:] = LN(x[b,t,:]) @ k1 + b1[0]
// ============================================================================
__global__ void __launch_bounds__(256)
k_ln_proj(const float* __restrict__ x, const float* __restrict__ gamma,
          const float* __restrict__ beta, const float* __restrict__ k1,
          const float* __restrict__ b1)
{
    __shared__ float xs[16][64];
    const int tid = threadIdx.x;
    const int w = tid >> 5, l = tid & 31;
    const size_t rowbase = (size_t)blockIdx.x * 16;

    #pragma unroll
    for (int rr = 0; rr < 2; rr++) {
        const int r = 2 * w + rr;
        const float* xr = x + (rowbase + r) * FF;
        float v0 = xr[l], v1 = xr[l + 32];
        float s = v0 + v1;
        #pragma unroll
        for (int o = 16; o; o >>= 1) s += __shfl_xor_sync(0xFFFFFFFFu, s, o);
        const float mu = s * (1.f / 64.f);
        const float d0 = v0 - mu, d1 = v1 - mu;
        float q = d0 * d0 + d1 * d1;
        #pragma unroll
        for (int o = 16; o; o >>= 1) q += __shfl_xor_sync(0xFFFFFFFFu, q, o);
        const float rstd = rsqrtf(q * (1.f / 64.f) + EPSF);
        xs[r][l]      = d0 * rstd * gamma[l]      + beta[l];
        xs[r][l + 32] = d1 * rstd * gamma[l + 32] + beta[l + 32];
    }
    __syncthreads();

    float acc[3][16];
    #pragma unroll
    for (int j = 0; j < 3; j++) {
        const float b = b1[tid + j * 256];
        #pragma unroll
        for (int r = 0; r < 16; r++) acc[j][r] = b;
    }
    for (int k = 0; k < 64; k++) {
        const float w0 = __ldg(k1 + k * G3 + tid);
        const float w1 = __ldg(k1 + k * G3 + tid + 256);
        const float w2 = __ldg(k1 + k * G3 + tid + 512);
        #pragma unroll
        for (int r = 0; r < 16; r++) {
            const float xv = xs[r][k];
            acc[0][r] = fmaf(xv, w0, acc[0][r]);
            acc[1][r] = fmaf(xv, w1, acc[1][r]);
            acc[2][r] = fmaf(xv, w2, acc[2][r]);
        }
    }
    #pragma unroll
    for (int r = 0; r < 16; r++) {
        float* o = g_xb1 + (rowbase + r) * G3;
        o[tid]       = acc[0][r];
        o[tid + 256] = acc[1][r];
        o[tid + 512] = acc[2][r];
    }
}

// ============================================================================
// GRU recurrence. Cluster of 8 CTAs = 2 batches. 384 threads:
//   thread = (kq in 0..3 [64-k quarter], col in 0..95 [gate column slice]).
//   rk slice register-resident as f32x2 pairs; k2 slice (PROJ) in padded SMEM.
//   Per-step h broadcast via st.shared::cluster; one split arrive/wait cluster
//   barrier per step with the xb2 global store in the drain gap.
// ============================================================================
template<bool PROJ>
__global__ void __launch_bounds__(THREADS, 1) __cluster_dims__(CLUSTER, 1, 1)
k_gru(const float* __restrict__ rk, const float* __restrict__ bias,
      const float* __restrict__ kproj, const float* __restrict__ bproj)
{
    extern __shared__ __align__(16) float sm[];
    constexpr int WKF = PROJ ? 96 * 260 : 0;
    float* Wk   = sm;                       // [96][260] padded (PROJ only)
    float* hbuf = sm + WKF;                 // [2 parity][2 b][256]
    float* base = hbuf + 1024;
    ull*   scR  = (ull*)base;                         // [4 kq][96] packed (b0,b1)
    ull*   scK  = (ull*)(base + 768);                 // PROJ only
    float* xbb  = base + 768 + (PROJ ? 768 : 0);      // [2 b][96]
    float* rb   = xbb + 192;                          // [96]
    float* kb   = rb + 96;                            // [96]

    const int tid  = threadIdx.x;
    const uint32_t rank = cluster_rank();
    const int b0 = (blockIdx.x / CLUSTER) * 2;
    const int warp = tid >> 5, lane = tid & 31;
    const int kq  = warp & 3;
    const int col = (warp >> 2) * 32 + lane;
    const int gc  = (col >> 5) * 256 + (int)rank * 32 + (col & 31);

    // ---- stage rk slice into registers as (w_k, w_{k+1}) pairs ----
    ull wr[32];
    #pragma unroll
    for (int i = 0; i < 32; i++) {
        const int k = kq * 64 + 2 * i;
        wr[i] = pack2(__ldg(rk + (size_t)k * G3 + gc),
                      __ldg(rk + (size_t)(k + 1) * G3 + gc));
    }
    // ---- stage k2 slice into padded SMEM (column-major rows, LDS.128-friendly) ----
    if (PROJ) {
        for (int idx = tid; idx < 96 * 256; idx += THREADS) {
            const int k = idx / 96, c = idx % 96;
            const int g2 = (c >> 5) * 256 + (int)rank * 32 + (c & 31);
            Wk[c * 260 + k] = kproj[(size_t)k * G3 + g2];
        }
    }
    for (int c = tid; c < 96; c += THREADS) {
        const int g2 = (c >> 5) * 256 + (int)rank * 32 + (c & 31);
        rb[c] = bias[G3 + g2];
        if (PROJ) kb[c] = bproj[g2];
    }
    for (int i = tid; i < 1024; i += THREADS) hbuf[i] = 0.f;
    __syncthreads();
    cluster_sync_();

    // xb I/O roles (tid < 192)
    const int lb = tid / 96, lc = tid % 96;
    const int gcl = (lc >> 5) * 256 + (int)rank * 32 + (lc & 31);
    const float* xbp = (PROJ ? g_xb1 : g_xb2) + ((size_t)(b0 + lb) * TT) * G3 + gcl;
    float*       xbo = g_xb2 + ((size_t)(b0 + lb) * TT) * G3 + gcl;

    int p = 0;
    const int TMAX = PROJ ? TT + 1 : TT;
    for (int t = 0; t < TMAX; t++) {
        const bool live = (t < TT);           // uniform across the whole cluster
        float xv = 0.f;
        if (live && tid < 192) xv = __ldg(xbp + (size_t)t * G3);

        // ---- matvec over this thread's 64-k quarter, f32x2 over (k,k+1) ----
        const ulonglong2* hb  = (const ulonglong2*)(hbuf + p * 512);
        const ulonglong2* hb0 = hb + kq * 16;        // batch 0
        const ulonglong2* hb1 = hb + 64 + kq * 16;   // batch 1
        const ulonglong2* wk2 = PROJ ? (const ulonglong2*)(Wk + col * 260 + kq * 64) : nullptr;

        ull aR0b0 = 0, aR1b0 = 0, aR0b1 = 0, aR1b1 = 0;
        ull aK0b0 = 0, aK1b0 = 0, aK0b1 = 0, aK1b1 = 0;
        #pragma unroll
        for (int i = 0; i < 16; i++) {
            const ulonglong2 h0 = hb0[i];
            const ulonglong2 h1 = hb1[i];
            aR0b0 = fma2(wr[2 * i],     h0.x, aR0b0);
            aR1b0 = fma2(wr[2 * i + 1], h0.y, aR1b0);
            aR0b1 = fma2(wr[2 * i],     h1.x, aR0b1);
            aR1b1 = fma2(wr[2 * i + 1], h1.y, aR1b1);
            if (PROJ) {
                const ulonglong2 u = wk2[i];
                aK0b0 = fma2(u.x, h0.x, aK0b0);
                aK1b0 = fma2(u.y, h0.y, aK1b0);
                aK0b1 = fma2(u.x, h1.x, aK0b1);
                aK1b1 = fma2(u.y, h1.y, aK1b1);
            }
        }
        {
            const ull s0 = add2(aR0b0, aR1b0), s1 = add2(aR0b1, aR1b1);
            float a, b, c, d; unpack2(s0, a, b); unpack2(s1, c, d);
            scR[kq * 96 + col] = pack2(a + b, c + d);
            if (PROJ) {
                const ull k0 = add2(aK0b0, aK1b0), k1v = add2(aK0b1, aK1b1);
                float e, f, g, h; unpack2(k0, e, f); unpack2(k1v, g, h);
                scK[kq * 96 + col] = pack2(e + f, g + h);
            }
        }
        if (live && tid < 192) xbb[tid] = xv;
        __syncthreads();

        // ---- gates: 64 threads, one per (batch, h-index) ----
        if (live && tid < 64) {
            const int b = tid >> 5, hi = tid & 31;
            const int hg = (int)rank * 32 + hi;
            const float* sf = (const float*)scR;
            float sZ = sf[(0 * 96 + hi) * 2 + b] + sf[(1 * 96 + hi) * 2 + b]
                     + sf[(2 * 96 + hi) * 2 + b] + sf[(3 * 96 + hi) * 2 + b] + rb[hi];
            float sR = sf[(0 * 96 + 32 + hi) * 2 + b] + sf[(1 * 96 + 32 + hi) * 2 + b]
                     + sf[(2 * 96 + 32 + hi) * 2 + b] + sf[(3 * 96 + 32 + hi) * 2 + b] + rb[32 + hi];
            float sH = sf[(0 * 96 + 64 + hi) * 2 + b] + sf[(1 * 96 + 64 + hi) * 2 + b]
                     + sf[(2 * 96 + 64 + hi) * 2 + b] + sf[(3 * 96 + 64 + hi) * 2 + b] + rb[64 + hi];

            const float hp = hbuf[p * 512 + b * 256 + hg];
            const float z  = fsig(xbb[b * 96 + hi] + sZ);
            const float r  = fsig(xbb[b * 96 + 32 + hi] + sR);
            const float hh = ftanh(xbb[b * 96 + 64 + hi] + r * sH);
            const float hn = z * hp + (1.f - z) * hh;

            const uint32_t la = smem_u32(hbuf) + (uint32_t)(((p ^ 1) * 512 + b * 256 + hg) * 4);
            #pragma unroll
            for (int pr = 0; pr < CLUSTER; pr++) st_cluster_f32(la, hn, (uint32_t)pr);

            if (!PROJ && t == TT - 1) g_h2[(b0 + b) * HH + hg] = hn;
        }
        if (live) cluster_arrive_();

        // ---- overlap zone: write xb2[t-1] while the barrier drains ----
        if (PROJ && t > 0 && tid < 192) {
            const float* sk = (const float*)scK;
            const float v = sk[(0 * 96 + lc) * 2 + lb] + sk[(1 * 96 + lc) * 2 + lb]
                          + sk[(2 * 96 + lc) * 2 + lb] + sk[(3 * 96 + lc) * 2 + lb] + kb[lc];
            xbo[(size_t)(t - 1) * G3] = v;
        }
        if (live) cluster_wait_();
        p ^= 1;
    }
}

// ============================================================================
// Final dense.
// ============================================================================
__global__ void __launch_bounds__(64)
k_dense(const float* __restrict__ wd, const float* __restrict__ bd,
        float* __restrict__ out)
{
    __shared__ float hs[HH];
    const int b = blockIdx.x, o = threadIdx.x;
    for (int k = o; k < HH; k += 64) hs[k] = g_h2[b * HH + k];
    __syncthreads();
    float acc = bd[o];
    for (int k = 0; k < HH; k++) acc = fmaf(hs[k], __ldg(wd + k * OUTD + o), acc);
    out[b * OUTD + o] = acc;
}

// ============================================================================
extern "C" void kernel_launch(void* const* d_in, const int* in_sizes, int n_in,
                              void* d_out, int out_size)
{
    const float* x     = (const float*)d_in[0];
    const float* gamma = (const float*)d_in[1];
    const float* beta  = (const float*)d_in[2];
    const float* k1    = (const float*)d_in[3];
    const float* rk1   = (const float*)d_in[4];
    const float* b1    = (const float*)d_in[5];
    const float* k2    = (const float*)d_in[6];
    const float* rk2   = (const float*)d_in[7];
    const float* b2    = (const float*)d_in[8];
    const float* wd    = (const float*)d_in[9];
    const float* bd    = (const float*)d_in[10];
    float* out = (float*)d_out;

    const size_t smem1 = (size_t)(96 * 260 + 1024 + 768 + 768 + 192 + 96 + 96) * sizeof(float);
    const size_t smem2 = (size_t)(1024 + 768 + 192 + 96 + 96) * sizeof(float);
    cudaFuncSetAttribute(k_gru<true>,  cudaFuncAttributeMaxDynamicSharedMemorySize, (int)smem1);
    cudaFuncSetAttribute(k_gru<false>, cudaFuncAttributeMaxDynamicSharedMemorySize, (int)smem2);

    k_ln_proj<<<BATCH * TT / 16, 256>>>(x, gamma, beta, k1, b1);
    k_gru<true><<<NCTA, THREADS, smem1>>>(rk1, b1, k2, b2);
    k_gru<false><<<NCTA, THREADS, smem2>>>(rk2, b2, nullptr, nullptr);
    k_dense<<<BATCH, 64>>>(wd, bd, out);
}